// round 1
// baseline (speedup 1.0000x reference)
#include <cuda_runtime.h>
#include <cuda_bf16.h>
#include <math.h>

// Problem constants
#define B_   2
#define N_   2048
#define BQ_  32
#define BK_  128
#define NB_  64
#define CS_  384
#define CZ_  128
#define CH_  16
#define H_   12
#define PQK_ 4
#define PV_  8
#define ROWS_ (B_ * N_)          // 4096
#define PROJC_ 1152              // 192*3 + 144 + 432
#define FEATC_ 960               // H*(16 + 24 + 8 + 32)

// -------- scratch (static device globals; no allocation) --------
__device__ float g_sN   [ROWS_ * CS_];
__device__ float g_proj [ROWS_ * PROJC_];     // [q(192) | k(192) | v(192) | qp_raw(144) | kvp_raw(432)]
__device__ float g_qpts [ROWS_ * 144];        // rotated+translated q points
__device__ float g_kvpts[ROWS_ * 432];        // rotated+translated kv points
__device__ float g_qn   [ROWS_ * 12];
__device__ float g_kn   [ROWS_ * 12];
__device__ float g_feats[ROWS_ * FEATC_];
__device__ float g_Wcat [CS_ * PROJC_];       // concatenated projection weights
__device__ float g_Wzc  [CZ_ * 44];           // [Wb(12) | Wdz(32)] per CZ row

// -------- helpers --------
__device__ __forceinline__ float warpSum(float v) {
#pragma unroll
    for (int o = 16; o; o >>= 1) v += __shfl_xor_sync(0xffffffffu, v, o);
    return v;
}
__device__ __forceinline__ float warpMax(float v) {
#pragma unroll
    for (int o = 16; o; o >>= 1) v = fmaxf(v, __shfl_xor_sync(0xffffffffu, v, o));
    return v;
}

// -------- weight prep: concat projection weights + z weights --------
__global__ void prep_weights(const float* __restrict__ Wq, const float* __restrict__ Wk,
                             const float* __restrict__ Wv, const float* __restrict__ Wqp,
                             const float* __restrict__ Wkvp, const float* __restrict__ Wb,
                             const float* __restrict__ Wdz) {
    const int total1 = CS_ * PROJC_;
    const int total = total1 + CZ_ * 44;
    for (int i = blockIdx.x * blockDim.x + threadIdx.x; i < total; i += gridDim.x * blockDim.x) {
        if (i < total1) {
            int r = i / PROJC_, c = i % PROJC_;
            float w;
            if (c < 192)      w = Wq  [r * 192 + c];
            else if (c < 384) w = Wk  [r * 192 + (c - 192)];
            else if (c < 576) w = Wv  [r * 192 + (c - 384)];
            else if (c < 720) w = Wqp [r * 144 + (c - 576)];
            else              w = Wkvp[r * 432 + (c - 720)];
            g_Wcat[i] = w;
        } else {
            int j = i - total1;
            int r = j / 44, c = j % 44;
            g_Wzc[j] = (c < 12) ? Wb[r * 12 + c] : Wdz[r * 32 + (c - 12)];
        }
    }
}

// -------- LayerNorm of s --------
__global__ __launch_bounds__(128) void ln_s_kernel(const float* __restrict__ s,
                                                   const float* __restrict__ g,
                                                   const float* __restrict__ bb) {
    const int row = blockIdx.x;
    const int t = threadIdx.x;
    const float* x = s + (size_t)row * CS_;
    float a0 = x[t], a1 = x[t + 128], a2 = x[t + 256];
    float sum = a0 + a1 + a2;
    float sq = a0 * a0 + a1 * a1 + a2 * a2;
    __shared__ float rs[4], rq[4];
    float ws = warpSum(sum), wq = warpSum(sq);
    if ((t & 31) == 0) { rs[t >> 5] = ws; rq[t >> 5] = wq; }
    __syncthreads();
    float S = rs[0] + rs[1] + rs[2] + rs[3];
    float Q = rq[0] + rq[1] + rq[2] + rq[3];
    float m = S * (1.0f / 384.0f);
    float var = Q * (1.0f / 384.0f) - m * m;
    float inv = rsqrtf(var + 1e-5f);
    float* o = g_sN + (size_t)row * CS_;
    o[t]       = (a0 - m) * inv * g[t]       + bb[t];
    o[t + 128] = (a1 - m) * inv * g[t + 128] + bb[t + 128];
    o[t + 256] = (a2 - m) * inv * g[t + 256] + bb[t + 256];
}

// -------- generic fp32 tiled GEMM: C[M,N] = A[M,K] @ B[K,N], all row-major --------
// BM=64, BN=64, BK=16, 256 threads, 4x4 micro-tile. M%64==0, N%64==0, K%16==0.
__global__ __launch_bounds__(256) void gemm64x64(const float* __restrict__ A,
                                                 const float* __restrict__ B,
                                                 float* __restrict__ C,
                                                 int M, int N, int K) {
    __shared__ __align__(16) float As[16][66];
    __shared__ __align__(16) float Bs[16][68];
    const int tid = threadIdx.x;
    const int tx = tid & 15, ty = tid >> 4;
    const int bm = blockIdx.y << 6, bn = blockIdx.x << 6;
    const int a_row = tid >> 2;
    const int a_col = (tid & 3) << 2;
    const int b_row = tid >> 4;
    const int b_col = (tid & 15) << 2;
    float acc[4][4] = {};
    for (int k0 = 0; k0 < K; k0 += 16) {
        float4 av = *reinterpret_cast<const float4*>(A + (size_t)(bm + a_row) * K + k0 + a_col);
        As[a_col + 0][a_row] = av.x;
        As[a_col + 1][a_row] = av.y;
        As[a_col + 2][a_row] = av.z;
        As[a_col + 3][a_row] = av.w;
        float4 bv = *reinterpret_cast<const float4*>(B + (size_t)(k0 + b_row) * N + bn + b_col);
        *reinterpret_cast<float4*>(&Bs[b_row][b_col]) = bv;
        __syncthreads();
#pragma unroll
        for (int kk = 0; kk < 16; kk++) {
            float ar[4], br[4];
#pragma unroll
            for (int i = 0; i < 4; i++) ar[i] = As[kk][(ty << 2) + i];
#pragma unroll
            for (int j = 0; j < 4; j++) br[j] = Bs[kk][(tx << 2) + j];
#pragma unroll
            for (int i = 0; i < 4; i++)
#pragma unroll
                for (int j = 0; j < 4; j++) acc[i][j] += ar[i] * br[j];
        }
        __syncthreads();
    }
#pragma unroll
    for (int i = 0; i < 4; i++) {
        float* cp = C + (size_t)(bm + (ty << 2) + i) * N + bn + (tx << 2);
#pragma unroll
        for (int j = 0; j < 4; j++) cp[j] = acc[i][j];
    }
}

// -------- per-row point rotation + norms --------
__global__ __launch_bounds__(192) void postproj(const float* __restrict__ rots,
                                                const float* __restrict__ trans) {
    const int row = blockIdx.x;
    const int t = threadIdx.x;
    __shared__ float R[9], T[3], nrm[24];
    if (t < 9)  R[t] = rots[row * 9 + t];
    if (t < 3)  T[t] = trans[row * 3 + t];
    if (t < 24) nrm[t] = 0.0f;
    __syncthreads();
    const float* pr = g_proj + (size_t)row * PROJC_;
    float x, y, zz;
    if (t < 48) {
        x = pr[576 + t * 3]; y = pr[576 + t * 3 + 1]; zz = pr[576 + t * 3 + 2];
    } else {
        int j = t - 48;
        x = pr[720 + j * 3]; y = pr[720 + j * 3 + 1]; zz = pr[720 + j * 3 + 2];
    }
    float rx = R[0] * x + R[1] * y + R[2] * zz + T[0];
    float ry = R[3] * x + R[4] * y + R[5] * zz + T[1];
    float rz = R[6] * x + R[7] * y + R[8] * zz + T[2];
    float sq = rx * rx + ry * ry + rz * rz;
    if (t < 48) {
        g_qpts[row * 144 + t * 3 + 0] = rx;
        g_qpts[row * 144 + t * 3 + 1] = ry;
        g_qpts[row * 144 + t * 3 + 2] = rz;
        atomicAdd(&nrm[t >> 2], sq);
    } else {
        int j = t - 48;
        g_kvpts[(size_t)row * 432 + j * 3 + 0] = rx;
        g_kvpts[(size_t)row * 432 + j * 3 + 1] = ry;
        g_kvpts[(size_t)row * 432 + j * 3 + 2] = rz;
        if ((j % 12) < 4) atomicAdd(&nrm[12 + j / 12], sq);
    }
    __syncthreads();
    if (t < 12)       g_qn[row * 12 + t] = nrm[t];
    else if (t < 24)  g_kn[row * 12 + (t - 12)] = nrm[t];
}

// -------- fused attention kernel: one block per (b, nb, q) row --------
__global__ __launch_bounds__(256) void attn_kernel(const float* __restrict__ z,
                                                   const float* __restrict__ trans,
                                                   const float* __restrict__ rots,
                                                   const float* __restrict__ s_mask,
                                                   const int* __restrict__ key_idx,
                                                   const float* __restrict__ ln_z_g,
                                                   const float* __restrict__ ln_z_b,
                                                   const float* __restrict__ head_w) {
    const int blk = blockIdx.x;
    const int q  = blk & 31;
    const int nb = (blk >> 5) & 63;
    const int b  = blk >> 11;
    const int tid = threadIdx.x;
    const int lane = tid & 31, warp = tid >> 5;

    __shared__ float s_pz[128 * 32];     // pair_z per key
    __shared__ float s_bb[128 * 12];     // bbias per key
    __shared__ float s_logit[12 * 128];  // logits -> softmax probs
    __shared__ float s_zn[8][128];
    __shared__ float s_q[192], s_qpts[144], s_qn[12], s_hw[12];
    __shared__ float s_R[9], s_t[3], s_km[128];
    __shared__ int   s_kid[128];
    __shared__ float s_opt[288];
    __shared__ float s_qm;

    const int row = b * N_ + nb * 32 + q;
    for (int i = tid; i < 192; i += 256) s_q[i]    = g_proj[(size_t)row * PROJC_ + i];
    for (int i = tid; i < 144; i += 256) s_qpts[i] = g_qpts[row * 144 + i];
    if (tid < 12) {
        s_qn[tid] = g_qn[row * 12 + tid];
        float hx = head_w[tid];
        float sp = fmaxf(hx, 0.0f) + log1pf(expf(-fabsf(hx)));   // softplus, robust
        s_hw[tid] = -0.5f * sp * 0.13608276348795434f;            // * sqrt(1/54)
    }
    if (tid < 9) s_R[tid] = rots[row * 9 + tid];
    if (tid < 3) s_t[tid] = trans[row * 3 + tid];
    if (tid == 0) s_qm = s_mask[row];
    for (int k = tid; k < 128; k += 256) {
        int nk = key_idx[nb * 128 + k];
        s_kid[k] = nk;
        s_km[k] = s_mask[b * N_ + nk];
    }

    // ---- phase 1: z rows -> LN -> bbias + pair_z ----
    float g0 = ln_z_g[lane], g1 = ln_z_g[32 + lane], g2 = ln_z_g[64 + lane], g3 = ln_z_g[96 + lane];
    float e0 = ln_z_b[lane], e1 = ln_z_b[32 + lane], e2 = ln_z_b[64 + lane], e3 = ln_z_b[96 + lane];
    const float* zbase = z + ((size_t)((b * 64 + nb) * 32 + q) * 128) * 128;
    for (int k = warp; k < 128; k += 8) {
        const float* zr = zbase + (size_t)k * 128;
        float x0 = zr[lane], x1 = zr[32 + lane], x2 = zr[64 + lane], x3 = zr[96 + lane];
        float m = warpSum(x0 + x1 + x2 + x3) * (1.0f / 128.0f);
        float d0 = x0 - m, d1 = x1 - m, d2 = x2 - m, d3 = x3 - m;
        float var = warpSum(d0 * d0 + d1 * d1 + d2 * d2 + d3 * d3) * (1.0f / 128.0f);
        float inv = rsqrtf(var + 1e-5f);
        s_zn[warp][lane]      = d0 * inv * g0 + e0;
        s_zn[warp][lane + 32] = d1 * inv * g1 + e1;
        s_zn[warp][lane + 64] = d2 * inv * g2 + e2;
        s_zn[warp][lane + 96] = d3 * inv * g3 + e3;
        __syncwarp();
        float acc1 = 0.0f, acc2 = 0.0f;
        const bool has2 = lane < 12;
#pragma unroll 4
        for (int r = 0; r < 128; r++) {
            float zv = s_zn[warp][r];
            acc1 += zv * g_Wzc[r * 44 + lane];
            if (has2) acc2 += zv * g_Wzc[r * 44 + 32 + lane];
        }
        if (lane < 12) {
            s_bb[k * 12 + lane] = acc1;          // bbias cols 0..11
            s_pz[k * 32 + 20 + lane] = acc2;     // pair_z cols 20..31
        } else {
            s_pz[k * 32 + (lane - 12)] = acc1;   // pair_z cols 0..19
        }
        __syncwarp();
    }
    __syncthreads();

    // ---- phase 2: logits ----
    const float qm = s_qm;
    for (int l = tid; l < 1536; l += 256) {
        int h = l >> 7, k = l & 127;
        int krow = b * N_ + s_kid[k];
        const float* kp = g_proj + (size_t)krow * PROJC_ + 192 + h * 16;
        float dot = 0.0f;
#pragma unroll
        for (int c = 0; c < 16; c++) dot += s_q[h * 16 + c] * kp[c];
        const float* kpt = g_kvpts + (size_t)krow * 432 + h * 36;
        float pdot = 0.0f;
#pragma unroll
        for (int c = 0; c < 12; c++) pdot += s_qpts[h * 12 + c] * kpt[c];
        float pt = -2.0f * pdot + s_qn[h] + g_kn[krow * 12 + h];
        float lg = dot * 0.14433756729740643f                 // 1/sqrt(48)
                 + 0.5773502691896258f * s_bb[k * 12 + h]     // sqrt(1/3)
                 + s_hw[h] * pt
                 + 100000.0f * (qm * s_km[k] - 1.0f);
        s_logit[h * 128 + k] = lg;
    }
    __syncthreads();

    // ---- phase 3: softmax over k per head ----
    for (int h = warp; h < 12; h += 8) {
        float v0 = s_logit[h * 128 + lane],      v1 = s_logit[h * 128 + lane + 32];
        float v2 = s_logit[h * 128 + lane + 64], v3 = s_logit[h * 128 + lane + 96];
        float mx = warpMax(fmaxf(fmaxf(v0, v1), fmaxf(v2, v3)));
        v0 = expf(v0 - mx); v1 = expf(v1 - mx); v2 = expf(v2 - mx); v3 = expf(v3 - mx);
        float invs = 1.0f / warpSum(v0 + v1 + v2 + v3);
        s_logit[h * 128 + lane]      = v0 * invs;
        s_logit[h * 128 + lane + 32] = v1 * invs;
        s_logit[h * 128 + lane + 64] = v2 * invs;
        s_logit[h * 128 + lane + 96] = v3 * invs;
    }
    __syncthreads();

    // ---- phase 4: outputs ----
    float* frow = g_feats + (size_t)row * FEATC_;
    // o = a @ v  (192 outputs)
    if (tid < 192) {
        int h = tid >> 4, c = tid & 15;
        const float* a = &s_logit[h * 128];
        float acc = 0.0f;
#pragma unroll 4
        for (int k = 0; k < 128; k++)
            acc += a[k] * g_proj[(size_t)(b * N_ + s_kid[k]) * PROJC_ + 384 + h * 16 + c];
        frow[tid] = acc;
    }
    // o_pt raw = a @ v_pts (288 outputs)
    for (int o = tid; o < 288; o += 256) {
        int h = o / 24, r = o % 24;
        const float* a = &s_logit[h * 128];
        float acc = 0.0f;
#pragma unroll 4
        for (int k = 0; k < 128; k++)
            acc += a[k] * g_kvpts[(size_t)(b * N_ + s_kid[k]) * 432 + h * 36 + 12 + r];
        s_opt[o] = acc;
    }
    // o_pair = a @ pair_z (384 outputs, all from smem)
    for (int o = tid; o < 384; o += 256) {
        int h = o >> 5, c = o & 31;
        const float* a = &s_logit[h * 128];
        float acc = 0.0f;
#pragma unroll 4
        for (int k = 0; k < 128; k++)
            acc += a[k] * s_pz[k * 32 + c];
        frow[576 + o] = acc;
    }
    __syncthreads();
    // inverse-frame transform + norms
    for (int j = tid; j < 96; j += 256) {
        int h = j >> 3, vp = j & 7;
        float X0 = s_opt[h * 24 + vp * 3 + 0] - s_t[0];
        float X1 = s_opt[h * 24 + vp * 3 + 1] - s_t[1];
        float X2 = s_opt[h * 24 + vp * 3 + 2] - s_t[2];
        float Y0 = s_R[0] * X0 + s_R[3] * X1 + s_R[6] * X2;
        float Y1 = s_R[1] * X0 + s_R[4] * X1 + s_R[7] * X2;
        float Y2 = s_R[2] * X0 + s_R[5] * X1 + s_R[8] * X2;
        frow[192 + h * 24 + vp * 3 + 0] = Y0;
        frow[192 + h * 24 + vp * 3 + 1] = Y1;
        frow[192 + h * 24 + vp * 3 + 2] = Y2;
        frow[480 + h * 8 + vp] = sqrtf(Y0 * Y0 + Y1 * Y1 + Y2 * Y2 + 1e-8f);
    }
}

// -------- launch --------
extern "C" void kernel_launch(void* const* d_in, const int* in_sizes, int n_in,
                              void* d_out, int out_size) {
    const float* s       = (const float*)d_in[0];
    const float* z       = (const float*)d_in[1];
    const float* trans   = (const float*)d_in[2];
    const float* rots    = (const float*)d_in[3];
    const float* s_mask  = (const float*)d_in[4];
    const int*   key_idx = (const int*)d_in[5];
    const float* ln_s_g  = (const float*)d_in[6];
    const float* ln_s_b  = (const float*)d_in[7];
    const float* ln_z_g  = (const float*)d_in[8];
    const float* ln_z_b  = (const float*)d_in[9];
    const float* Wq      = (const float*)d_in[10];
    const float* Wk      = (const float*)d_in[11];
    const float* Wv      = (const float*)d_in[12];
    const float* Wqp     = (const float*)d_in[13];
    const float* Wkvp    = (const float*)d_in[14];
    const float* Wb      = (const float*)d_in[15];
    const float* Wdz     = (const float*)d_in[16];
    const float* hw      = (const float*)d_in[17];
    const float* Wout    = (const float*)d_in[18];
    float* out = (float*)d_out;

    void *p_sN, *p_Wcat, *p_proj, *p_feats;
    cudaGetSymbolAddress(&p_sN,    g_sN);
    cudaGetSymbolAddress(&p_Wcat,  g_Wcat);
    cudaGetSymbolAddress(&p_proj,  g_proj);
    cudaGetSymbolAddress(&p_feats, g_feats);

    prep_weights<<<256, 256>>>(Wq, Wk, Wv, Wqp, Wkvp, Wb, Wdz);
    ln_s_kernel<<<ROWS_, 128>>>(s, ln_s_g, ln_s_b);
    {
        dim3 grid(PROJC_ / 64, ROWS_ / 64);
        gemm64x64<<<grid, 256>>>((const float*)p_sN, (const float*)p_Wcat,
                                 (float*)p_proj, ROWS_, PROJC_, CS_);
    }
    postproj<<<ROWS_, 192>>>(rots, trans);
    attn_kernel<<<ROWS_, 256>>>(z, trans, rots, s_mask, key_idx, ln_z_g, ln_z_b, hw);
    {
        dim3 grid(CS_ / 64, ROWS_ / 64);
        gemm64x64<<<grid, 256>>>((const float*)p_feats, Wout,
                                 out, ROWS_, CS_, FEATC_);
    }
    (void)in_sizes; (void)n_in; (void)out_size;
}

// round 2
// speedup vs baseline: 1.2032x; 1.2032x over previous
#include <cuda_runtime.h>
#include <cuda_bf16.h>
#include <math.h>

// Problem constants
#define B_   2
#define N_   2048
#define BQ_  32
#define BK_  128
#define NB_  64
#define CS_  384
#define CZ_  128
#define CH_  16
#define H_   12
#define PQK_ 4
#define PV_  8
#define ROWS_ (B_ * N_)          // 4096
#define PROJC_ 1152              // 192*3 + 144 + 432
#define FEATC_ 960               // H*(16 + 24 + 8 + 32)

// -------- scratch (static device globals; no allocation) --------
__device__ float g_sN   [ROWS_ * CS_];
__device__ float g_proj [ROWS_ * PROJC_];     // [q(192) | k(192) | v(192) | qp_raw(144) | kvp_raw(432)]
__device__ float g_qpts [ROWS_ * 144];
__device__ float g_kvpts[ROWS_ * 432];
__device__ float g_qn   [ROWS_ * 12];
__device__ float g_kn   [ROWS_ * 12];
__device__ float g_feats[ROWS_ * FEATC_];
__device__ float g_Wcat [CS_ * PROJC_];       // concatenated projection weights (Wq pre-scaled)
__device__ float g_Wzc  [CZ_ * 44];           // [Wb*sqrt(1/3) (12) | Wdz (32)] per CZ row

// -------- helpers --------
__device__ __forceinline__ float warpSum(float v) {
#pragma unroll
    for (int o = 16; o; o >>= 1) v += __shfl_xor_sync(0xffffffffu, v, o);
    return v;
}
__device__ __forceinline__ float warpMax(float v) {
#pragma unroll
    for (int o = 16; o; o >>= 1) v = fmaxf(v, __shfl_xor_sync(0xffffffffu, v, o));
    return v;
}

// -------- weight prep --------
__global__ void prep_weights(const float* __restrict__ Wq, const float* __restrict__ Wk,
                             const float* __restrict__ Wv, const float* __restrict__ Wqp,
                             const float* __restrict__ Wkvp, const float* __restrict__ Wb,
                             const float* __restrict__ Wdz) {
    const int total1 = CS_ * PROJC_;
    const int total = total1 + CZ_ * 44;
    for (int i = blockIdx.x * blockDim.x + threadIdx.x; i < total; i += gridDim.x * blockDim.x) {
        if (i < total1) {
            int r = i / PROJC_, c = i % PROJC_;
            float w;
            if (c < 192)      w = Wq  [r * 192 + c] * 0.14433756729740643f;  // 1/sqrt(48)
            else if (c < 384) w = Wk  [r * 192 + (c - 192)];
            else if (c < 576) w = Wv  [r * 192 + (c - 384)];
            else if (c < 720) w = Wqp [r * 144 + (c - 576)];
            else              w = Wkvp[r * 432 + (c - 720)];
            g_Wcat[i] = w;
        } else {
            int j = i - total1;
            int r = j / 44, c = j % 44;
            g_Wzc[j] = (c < 12) ? Wb[r * 12 + c] * 0.5773502691896258f  // sqrt(1/3)
                                : Wdz[r * 32 + (c - 12)];
        }
    }
}

// -------- LayerNorm of s --------
__global__ __launch_bounds__(128) void ln_s_kernel(const float* __restrict__ s,
                                                   const float* __restrict__ g,
                                                   const float* __restrict__ bb) {
    const int row = blockIdx.x;
    const int t = threadIdx.x;
    const float* x = s + (size_t)row * CS_;
    float a0 = x[t], a1 = x[t + 128], a2 = x[t + 256];
    float sum = a0 + a1 + a2;
    float sq = a0 * a0 + a1 * a1 + a2 * a2;
    __shared__ float rs[4], rq[4];
    float ws = warpSum(sum), wq = warpSum(sq);
    if ((t & 31) == 0) { rs[t >> 5] = ws; rq[t >> 5] = wq; }
    __syncthreads();
    float S = rs[0] + rs[1] + rs[2] + rs[3];
    float Q = rq[0] + rq[1] + rq[2] + rq[3];
    float m = S * (1.0f / 384.0f);
    float var = Q * (1.0f / 384.0f) - m * m;
    float inv = rsqrtf(var + 1e-5f);
    float* o = g_sN + (size_t)row * CS_;
    o[t]       = (a0 - m) * inv * g[t]       + bb[t];
    o[t + 128] = (a1 - m) * inv * g[t + 128] + bb[t + 128];
    o[t + 256] = (a2 - m) * inv * g[t + 256] + bb[t + 256];
}

// -------- fp32 SGEMM: C[M,N] = A[M,K] @ B[K,N] row-major --------
// 128x128 block tile, 16 k-tile, 256 threads, 8x8 microtile, register prefetch.
// Requires M%128==0, N%128==0, K%16==0.
__global__ __launch_bounds__(256) void sgemm128(const float* __restrict__ A,
                                                const float* __restrict__ B,
                                                float* __restrict__ C,
                                                int M, int N, int K) {
    __shared__ __align__(16) float As[16][132];  // transposed A tile (k-major)
    __shared__ __align__(16) float Bs[16][128];
    const int tid = threadIdx.x;
    const int bm = blockIdx.y << 7, bn = blockIdx.x << 7;
    const int ar = tid >> 2, ac = (tid & 3) << 2;     // A: rows ar, ar+64; cols ac..ac+3
    const int br = tid >> 5, bc = (tid & 31) << 2;    // B: rows br, br+8;  cols bc..bc+3
    const int tx = tid & 15, ty = tid >> 4;

    const float* Ap = A + (size_t)(bm + ar) * K + ac;
    const float* Bp = B + (size_t)br * N + bn + bc;
    const size_t A64 = (size_t)64 * K;
    const size_t B8  = (size_t)8 * N;

    float4 a0 = *reinterpret_cast<const float4*>(Ap);
    float4 a1 = *reinterpret_cast<const float4*>(Ap + A64);
    float4 b0 = *reinterpret_cast<const float4*>(Bp);
    float4 b1 = *reinterpret_cast<const float4*>(Bp + B8);

    float acc[8][8] = {};
    const int ktiles = K >> 4;
    for (int kt = 0; kt < ktiles; kt++) {
        // commit staged tile to smem
        As[ac + 0][ar] = a0.x; As[ac + 1][ar] = a0.y; As[ac + 2][ar] = a0.z; As[ac + 3][ar] = a0.w;
        As[ac + 0][ar + 64] = a1.x; As[ac + 1][ar + 64] = a1.y;
        As[ac + 2][ar + 64] = a1.z; As[ac + 3][ar + 64] = a1.w;
        *reinterpret_cast<float4*>(&Bs[br][bc])     = b0;
        *reinterpret_cast<float4*>(&Bs[br + 8][bc]) = b1;
        __syncthreads();
        if (kt + 1 < ktiles) {
            Ap += 16; Bp += (size_t)16 * N;
            a0 = *reinterpret_cast<const float4*>(Ap);
            a1 = *reinterpret_cast<const float4*>(Ap + A64);
            b0 = *reinterpret_cast<const float4*>(Bp);
            b1 = *reinterpret_cast<const float4*>(Bp + B8);
        }
#pragma unroll
        for (int kk = 0; kk < 16; kk++) {
            float ar_[8], br_[8];
            *reinterpret_cast<float4*>(ar_)     = *reinterpret_cast<const float4*>(&As[kk][ty * 8]);
            *reinterpret_cast<float4*>(ar_ + 4) = *reinterpret_cast<const float4*>(&As[kk][ty * 8 + 4]);
            *reinterpret_cast<float4*>(br_)     = *reinterpret_cast<const float4*>(&Bs[kk][tx * 8]);
            *reinterpret_cast<float4*>(br_ + 4) = *reinterpret_cast<const float4*>(&Bs[kk][tx * 8 + 4]);
#pragma unroll
            for (int i = 0; i < 8; i++)
#pragma unroll
                for (int j = 0; j < 8; j++) acc[i][j] += ar_[i] * br_[j];
        }
        __syncthreads();
    }
#pragma unroll
    for (int i = 0; i < 8; i++) {
        float* cp = C + (size_t)(bm + ty * 8 + i) * N + bn + tx * 8;
        *reinterpret_cast<float4*>(cp)     = *reinterpret_cast<float4*>(&acc[i][0]);
        *reinterpret_cast<float4*>(cp + 4) = *reinterpret_cast<float4*>(&acc[i][4]);
    }
}

// -------- per-row point rotation + norms --------
__global__ __launch_bounds__(192) void postproj(const float* __restrict__ rots,
                                                const float* __restrict__ trans) {
    const int row = blockIdx.x;
    const int t = threadIdx.x;
    __shared__ float R[9], T[3], nrm[24];
    if (t < 9)  R[t] = rots[row * 9 + t];
    if (t < 3)  T[t] = trans[row * 3 + t];
    if (t < 24) nrm[t] = 0.0f;
    __syncthreads();
    const float* pr = g_proj + (size_t)row * PROJC_;
    float x, y, zz;
    if (t < 48) {
        x = pr[576 + t * 3]; y = pr[576 + t * 3 + 1]; zz = pr[576 + t * 3 + 2];
    } else {
        int j = t - 48;
        x = pr[720 + j * 3]; y = pr[720 + j * 3 + 1]; zz = pr[720 + j * 3 + 2];
    }
    float rx = R[0] * x + R[1] * y + R[2] * zz + T[0];
    float ry = R[3] * x + R[4] * y + R[5] * zz + T[1];
    float rz = R[6] * x + R[7] * y + R[8] * zz + T[2];
    float sq = rx * rx + ry * ry + rz * rz;
    if (t < 48) {
        g_qpts[row * 144 + t * 3 + 0] = rx;
        g_qpts[row * 144 + t * 3 + 1] = ry;
        g_qpts[row * 144 + t * 3 + 2] = rz;
        atomicAdd(&nrm[t >> 2], sq);
    } else {
        int j = t - 48;
        g_kvpts[(size_t)row * 432 + j * 3 + 0] = rx;
        g_kvpts[(size_t)row * 432 + j * 3 + 1] = ry;
        g_kvpts[(size_t)row * 432 + j * 3 + 2] = rz;
        if ((j % 12) < 4) atomicAdd(&nrm[12 + j / 12], sq);
    }
    __syncthreads();
    if (t < 12)       g_qn[row * 12 + t] = nrm[t];
    else if (t < 24)  g_kn[row * 12 + (t - 12)] = nrm[t];
}

// -------- fused attention kernel: one block per (b, nb, q) --------
struct AttnSmem {
    float W[128][48];        // z weights: cols 0..11 bbias(pre-scaled), 12..43 pair_z, 44..47 zero
    float zn[64][132];       // LayerNormed z rows (one 64-key pass at a time)
    float pz[128][32];       // pair_z per key
    float bb[128][12];       // bbias per key
    float logit[12][128];    // logits -> softmax probs
    float q[192], qpts[144], qn[12], hw[12];
    float R[9], t[3], km[128], opt[288], qm;
    int   kid[128];
};

__global__ __launch_bounds__(256) void attn_kernel(const float* __restrict__ z,
                                                   const float* __restrict__ trans,
                                                   const float* __restrict__ rots,
                                                   const float* __restrict__ s_mask,
                                                   const int* __restrict__ key_idx,
                                                   const float* __restrict__ ln_z_g,
                                                   const float* __restrict__ ln_z_b,
                                                   const float* __restrict__ head_w) {
    extern __shared__ __align__(16) char smem_raw[];
    AttnSmem& S = *reinterpret_cast<AttnSmem*>(smem_raw);

    const int blk = blockIdx.x;
    const int q  = blk & 31;
    const int nb = (blk >> 5) & 63;
    const int b  = blk >> 11;
    const int tid = threadIdx.x;
    const int lane = tid & 31, warp = tid >> 5;
    const int row = b * N_ + nb * 32 + q;

    // ---- block-invariant loads ----
    for (int i = tid; i < 128 * 48; i += 256) {
        int r = i / 48, c = i % 48;
        S.W[r][c] = (c < 44) ? g_Wzc[r * 44 + c] : 0.0f;
    }
    for (int i = tid; i < 192; i += 256) S.q[i]    = g_proj[(size_t)row * PROJC_ + i];
    for (int i = tid; i < 144; i += 256) S.qpts[i] = g_qpts[row * 144 + i];
    if (tid < 12) {
        S.qn[tid] = g_qn[row * 12 + tid];
        float hx = head_w[tid];
        float sp = fmaxf(hx, 0.0f) + log1pf(expf(-fabsf(hx)));   // softplus
        S.hw[tid] = -0.5f * sp * 0.13608276348795434f;            // * sqrt(1/54)
    }
    if (tid < 9) S.R[tid] = rots[row * 9 + tid];
    if (tid < 3) S.t[tid] = trans[row * 3 + tid];
    if (tid == 0) S.qm = s_mask[row];
    for (int k = tid; k < 128; k += 256) {
        int nk = key_idx[nb * 128 + k];
        S.kid[k] = nk;
        S.km[k] = s_mask[b * N_ + nk];
    }

    // ---- phase 1: z LN + [bbias|pair_z] GEMM, two passes of 64 keys ----
    const float g0 = ln_z_g[lane], g1 = ln_z_g[32 + lane], g2 = ln_z_g[64 + lane], g3 = ln_z_g[96 + lane];
    const float e0 = ln_z_b[lane], e1 = ln_z_b[32 + lane], e2 = ln_z_b[64 + lane], e3 = ln_z_b[96 + lane];
    const float* zbase = z + ((size_t)((b * 64 + nb) * 32 + q) * 128) * 128;

    const int rg = tid >> 3;          // 0..31 : 2 key-rows each
    const int cg = tid & 7;           // 0..7  : 6 cols each
    const int r0 = rg * 2;

    for (int pass = 0; pass < 2; pass++) {
        const int kbase = pass * 64;
        // LN of 64 rows (8 warps x 8 rows)
        for (int kr = warp; kr < 64; kr += 8) {
            const float* zr = zbase + (size_t)(kbase + kr) * 128;
            float x0 = zr[lane], x1 = zr[32 + lane], x2 = zr[64 + lane], x3 = zr[96 + lane];
            float m = warpSum(x0 + x1 + x2 + x3) * (1.0f / 128.0f);
            float d0 = x0 - m, d1 = x1 - m, d2 = x2 - m, d3 = x3 - m;
            float var = warpSum(d0 * d0 + d1 * d1 + d2 * d2 + d3 * d3) * (1.0f / 128.0f);
            float inv = rsqrtf(var + 1e-5f);
            S.zn[kr][lane]      = d0 * inv * g0 + e0;
            S.zn[kr][lane + 32] = d1 * inv * g1 + e1;
            S.zn[kr][lane + 64] = d2 * inv * g2 + e2;
            S.zn[kr][lane + 96] = d3 * inv * g3 + e3;
        }
        __syncthreads();

        // block GEMM: C[64,48] = zn[64,128] @ W[128,48]; micro 2x6
        float acc[2][6] = {};
#pragma unroll 4
        for (int c = 0; c < 128; c++) {
            float a0 = S.zn[r0][c];
            float a1 = S.zn[r0 + 1][c];
            float2 w01 = *reinterpret_cast<const float2*>(&S.W[c][cg * 6]);
            float2 w23 = *reinterpret_cast<const float2*>(&S.W[c][cg * 6 + 2]);
            float2 w45 = *reinterpret_cast<const float2*>(&S.W[c][cg * 6 + 4]);
            acc[0][0] += a0 * w01.x; acc[0][1] += a0 * w01.y;
            acc[0][2] += a0 * w23.x; acc[0][3] += a0 * w23.y;
            acc[0][4] += a0 * w45.x; acc[0][5] += a0 * w45.y;
            acc[1][0] += a1 * w01.x; acc[1][1] += a1 * w01.y;
            acc[1][2] += a1 * w23.x; acc[1][3] += a1 * w23.y;
            acc[1][4] += a1 * w45.x; acc[1][5] += a1 * w45.y;
        }
#pragma unroll
        for (int i = 0; i < 2; i++) {
            int key = kbase + r0 + i;
#pragma unroll
            for (int j = 0; j < 6; j++) {
                int col = cg * 6 + j;
                if (col < 12)       S.bb[key][col] = acc[i][j];
                else if (col < 44)  S.pz[key][col - 12] = acc[i][j];
            }
        }
        __syncthreads();
    }

    // ---- phase 2: logits ----
    const float qm = S.qm;
    for (int l = tid; l < 1536; l += 256) {
        int h = l >> 7, k = l & 127;
        int krow = b * N_ + S.kid[k];
        const float* kp = g_proj + (size_t)krow * PROJC_ + 192 + h * 16;
        float dot = 0.0f;
#pragma unroll
        for (int c = 0; c < 16; c++) dot += S.q[h * 16 + c] * kp[c];
        const float* kpt = g_kvpts + (size_t)krow * 432 + h * 36;
        float pdot = 0.0f;
#pragma unroll
        for (int c = 0; c < 12; c++) pdot += S.qpts[h * 12 + c] * kpt[c];
        float pt = -2.0f * pdot + S.qn[h] + g_kn[krow * 12 + h];
        float lg = dot + S.bb[k][h] + S.hw[h] * pt + 100000.0f * (qm * S.km[k] - 1.0f);
        S.logit[h][k] = lg;
    }
    __syncthreads();

    // ---- phase 3: softmax over k per head ----
    for (int h = warp; h < 12; h += 8) {
        float v0 = S.logit[h][lane],      v1 = S.logit[h][lane + 32];
        float v2 = S.logit[h][lane + 64], v3 = S.logit[h][lane + 96];
        float mx = warpMax(fmaxf(fmaxf(v0, v1), fmaxf(v2, v3)));
        v0 = expf(v0 - mx); v1 = expf(v1 - mx); v2 = expf(v2 - mx); v3 = expf(v3 - mx);
        float invs = 1.0f / warpSum(v0 + v1 + v2 + v3);
        S.logit[h][lane]      = v0 * invs;
        S.logit[h][lane + 32] = v1 * invs;
        S.logit[h][lane + 64] = v2 * invs;
        S.logit[h][lane + 96] = v3 * invs;
    }
    __syncthreads();

    // ---- phase 4: outputs ----
    float* frow = g_feats + (size_t)row * FEATC_;
    if (tid < 192) {
        int h = tid >> 4, c = tid & 15;
        const float* a = &S.logit[h][0];
        float acc = 0.0f;
#pragma unroll 4
        for (int k = 0; k < 128; k++)
            acc += a[k] * g_proj[(size_t)(b * N_ + S.kid[k]) * PROJC_ + 384 + h * 16 + c];
        frow[tid] = acc;
    }
    for (int o = tid; o < 288; o += 256) {
        int h = o / 24, r = o % 24;
        const float* a = &S.logit[h][0];
        float acc = 0.0f;
#pragma unroll 4
        for (int k = 0; k < 128; k++)
            acc += a[k] * g_kvpts[(size_t)(b * N_ + S.kid[k]) * 432 + h * 36 + 12 + r];
        S.opt[o] = acc;
    }
    for (int o = tid; o < 384; o += 256) {
        int h = o >> 5, c = o & 31;
        const float* a = &S.logit[h][0];
        float acc = 0.0f;
#pragma unroll 4
        for (int k = 0; k < 128; k++)
            acc += a[k] * S.pz[k][c];
        frow[576 + o] = acc;
    }
    __syncthreads();
    for (int j = tid; j < 96; j += 256) {
        int h = j >> 3, vp = j & 7;
        float X0 = S.opt[h * 24 + vp * 3 + 0] - S.t[0];
        float X1 = S.opt[h * 24 + vp * 3 + 1] - S.t[1];
        float X2 = S.opt[h * 24 + vp * 3 + 2] - S.t[2];
        float Y0 = S.R[0] * X0 + S.R[3] * X1 + S.R[6] * X2;
        float Y1 = S.R[1] * X0 + S.R[4] * X1 + S.R[7] * X2;
        float Y2 = S.R[2] * X0 + S.R[5] * X1 + S.R[8] * X2;
        frow[192 + h * 24 + vp * 3 + 0] = Y0;
        frow[192 + h * 24 + vp * 3 + 1] = Y1;
        frow[192 + h * 24 + vp * 3 + 2] = Y2;
        frow[480 + h * 8 + vp] = sqrtf(Y0 * Y0 + Y1 * Y1 + Y2 * Y2 + 1e-8f);
    }
}

// -------- launch --------
extern "C" void kernel_launch(void* const* d_in, const int* in_sizes, int n_in,
                              void* d_out, int out_size) {
    const float* s       = (const float*)d_in[0];
    const float* z       = (const float*)d_in[1];
    const float* trans   = (const float*)d_in[2];
    const float* rots    = (const float*)d_in[3];
    const float* s_mask  = (const float*)d_in[4];
    const int*   key_idx = (const int*)d_in[5];
    const float* ln_s_g  = (const float*)d_in[6];
    const float* ln_s_b  = (const float*)d_in[7];
    const float* ln_z_g  = (const float*)d_in[8];
    const float* ln_z_b  = (const float*)d_in[9];
    const float* Wq      = (const float*)d_in[10];
    const float* Wk      = (const float*)d_in[11];
    const float* Wv      = (const float*)d_in[12];
    const float* Wqp     = (const float*)d_in[13];
    const float* Wkvp    = (const float*)d_in[14];
    const float* Wb      = (const float*)d_in[15];
    const float* Wdz     = (const float*)d_in[16];
    const float* hw      = (const float*)d_in[17];
    const float* Wout    = (const float*)d_in[18];
    float* out = (float*)d_out;

    void *p_sN, *p_Wcat, *p_proj, *p_feats;
    cudaGetSymbolAddress(&p_sN,    g_sN);
    cudaGetSymbolAddress(&p_Wcat,  g_Wcat);
    cudaGetSymbolAddress(&p_proj,  g_proj);
    cudaGetSymbolAddress(&p_feats, g_feats);

    cudaFuncSetAttribute(attn_kernel, cudaFuncAttributeMaxDynamicSharedMemorySize,
                         (int)sizeof(AttnSmem));

    prep_weights<<<256, 256>>>(Wq, Wk, Wv, Wqp, Wkvp, Wb, Wdz);
    ln_s_kernel<<<ROWS_, 128>>>(s, ln_s_g, ln_s_b);
    {
        dim3 grid(PROJC_ / 128, ROWS_ / 128);  // 9 x 32
        sgemm128<<<grid, 256>>>((const float*)p_sN, (const float*)p_Wcat,
                                (float*)p_proj, ROWS_, PROJC_, CS_);
    }
    postproj<<<ROWS_, 192>>>(rots, trans);
    attn_kernel<<<ROWS_, 256, sizeof(AttnSmem)>>>(z, trans, rots, s_mask, key_idx,
                                                  ln_z_g, ln_z_b, hw);
    {
        dim3 grid(CS_ / 128, ROWS_ / 128);     // 3 x 32
        sgemm128<<<grid, 256>>>((const float*)p_feats, Wout,
                                out, ROWS_, CS_, FEATC_);
    }
    (void)in_sizes; (void)n_in; (void)out_size;
}